// round 11
// baseline (speedup 1.0000x reference)
#include <cuda_runtime.h>
#include <math.h>

#define HEADS 4
#define RES 28
#define PSZ 14
#define PP 196
#define NB 32
#define NT 784
#define NC 768
#define CH 192
#define NCT 24            // channel tiles of 32
#define EPSF 1e-5f

#define NTILES (NB * NCT)        // 768
#define WAVE1  592               // 4 blocks/SM x 148 SMs
#define NSPLIT (NTILES - WAVE1)  // 176 tiles handled by 2 half-epilogue blocks each
#define K2GRID (WAVE1 + 2 * NSPLIT)   // 944

// ---- persistent device scratch (no allocations allowed) ----
__device__ float g_xp[(size_t)NB * NCT * PP * 32];  // pooled xn, [b][ctile][patch][32]
__device__ float g_inv[NB * HEADS * NT];            // [b][h][t]
__device__ float g_mln[NB * NT];
__device__ float g_vln[NB * NT];

// ============================================================
// K1: per-token group stats + pooled xp.  block = (b, patch j)
// 192 threads; thread owns 4 consecutive channels (float4).
// ============================================================
__global__ void __launch_bounds__(192) k1_stats(const float* __restrict__ x) {
    int blk = blockIdx.x;
    int b = blk / PP, j = blk % PP;
    int py = j / 14, px = j % 14;
    int tid = threadIdx.x;
    int head = tid / 48;
    int c0 = head * CH + (tid % 48) * 4;
    int baseT = (2 * py) * 28 + 2 * px;

    float4 xv[4];
    float s1[4], s2[4];
    #pragma unroll
    for (int tok = 0; tok < 4; tok++) {
        int t = baseT + (tok >> 1) * 28 + (tok & 1);
        float4 v = __ldg((const float4*)(x + ((size_t)(b * NT + t)) * NC + c0));
        xv[tok] = v;
        s1[tok] = v.x + v.y + v.z + v.w;
        s2[tok] = v.x * v.x + v.y * v.y + v.z * v.z + v.w * v.w;
    }
    #pragma unroll
    for (int off = 8; off > 0; off >>= 1) {
        #pragma unroll
        for (int tok = 0; tok < 4; tok++) {
            s1[tok] += __shfl_down_sync(0xffffffffu, s1[tok], off, 16);
            s2[tok] += __shfl_down_sync(0xffffffffu, s2[tok], off, 16);
        }
    }
    __shared__ float rs1[12][4], rs2[12][4];            // [segment][tok]
    __shared__ float sS1[4][4], sS2[4][4], sInv[4][4];  // [tok][head]
    int seg = tid >> 4;
    if ((tid & 15) == 0) {
        #pragma unroll
        for (int tok = 0; tok < 4; tok++) { rs1[seg][tok] = s1[tok]; rs2[seg][tok] = s2[tok]; }
    }
    __syncthreads();
    if (tid < 16) {
        int tok = tid & 3, h = tid >> 2;
        float S1 = rs1[3 * h][tok] + rs1[3 * h + 1][tok] + rs1[3 * h + 2][tok];
        float S2 = rs2[3 * h][tok] + rs2[3 * h + 1][tok] + rs2[3 * h + 2][tok];
        float inv = rsqrtf(S2 * (1.0f / CH) + EPSF);
        sS1[tok][h] = S1; sS2[tok][h] = S2; sInv[tok][h] = inv;
        int t = baseT + (tok >> 1) * 28 + (tok & 1);
        g_inv[(b * HEADS + h) * NT + t] = inv;
    }
    __syncthreads();
    if (tid < 4) {
        int tok = tid;
        float sx = 0.f, sx2 = 0.f;
        #pragma unroll
        for (int h = 0; h < 4; h++) {
            float inv = sInv[tok][h];
            sx  += sS1[tok][h] * inv;
            sx2 += sS2[tok][h] * inv * inv;
        }
        float mean = sx * (1.0f / NC);
        float var = (sx2 - sx * mean) * (1.0f / (NC - 1));
        int t = baseT + (tok >> 1) * 28 + (tok & 1);
        g_mln[b * NT + t] = mean;
        g_vln[b * NT + t] = var;
    }
    float i0 = sInv[0][head], i1 = sInv[1][head], i2 = sInv[2][head], i3 = sInv[3][head];
    float4 o;
    o.x = 0.25f * (xv[0].x * i0 + xv[1].x * i1 + xv[2].x * i2 + xv[3].x * i3);
    o.y = 0.25f * (xv[0].y * i0 + xv[1].y * i1 + xv[2].y * i2 + xv[3].y * i3);
    o.z = 0.25f * (xv[0].z * i0 + xv[1].z * i1 + xv[2].z * i2 + xv[3].z * i3);
    o.w = 0.25f * (xv[0].w * i0 + xv[1].w * i1 + xv[2].w * i2 + xv[3].w * i3);
    int ct = c0 >> 5, ln = c0 & 31;
    *(float4*)&g_xp[(((size_t)(b * NCT + ct)) * PP + j) * 32 + ln] = o;
}

// ============================================================
// K2: separable pos-mix + fused output epilogue, wave-aware ragged grid.
// Blocks 0..591: full tile (all 28 image rows).
// Blocks 592..943: pairs covering tiles 592..767, each block = full mix
//   (smem-local, duplicated) + HALF the epilogue (14 image rows).
// block = 224 threads = 7 warps; warp g owns patch rows g, g+7.
// ============================================================
#define K2T 224
#define SM_FLOATS (12544 + 784 + 392)   // sT1,sT2 + sINV + sA,sB

__global__ void __launch_bounds__(K2T, 4) k2_main(
        const float* __restrict__ x, const float* __restrict__ weight,
        const float* __restrict__ bias, const float* __restrict__ mnw,
        const float* __restrict__ vnw, const float* __restrict__ pw,
        float* __restrict__ out) {
    extern __shared__ float sm[];
    float* sT1  = sm;              // 196x32 stage-1 mean     (later: scaled mean_r)
    float* sT2  = sm + 6272;       // 196x32 stage-1 sq-mean  (later: scaled var_r)
    float* sINV = sm + 12544;      // 784  inv for this head
    float* sA   = sm + 13328;      // 196  y-factor [iy*14+jy]
    float* sB   = sm + 13524;      // 196  x-factor [ix*14+jx]

    int bid = blockIdx.x;
    int tile, it0, itN;
    if (bid < WAVE1) {
        tile = bid; it0 = 0; itN = 4;            // full epilogue: 4 x 7 rows
    } else {
        int k = bid - WAVE1;
        tile = WAVE1 + (k % NSPLIT);
        it0 = (k / NSPLIT) * 2;                  // half epilogue: 2 x 7 rows
        itN = it0 + 2;
    }
    int b = tile / NCT;
    int ctile = tile % NCT;
    int c0 = ctile * 32;
    int h = ctile / 6;             // 6 tiles per head
    int tid = threadIdx.x;

    float mwh = 1.0f / (1.0f + expf(-mnw[h]));
    float vwh = 1.0f / (1.0f + expf(-vnw[h]));
    float omm = 1.0f - mwh, omv = 1.0f - vwh;

    // in-block separable softmax factors (pos_b cancels in softmax)
    if (tid < 14) {                       // Bn: x-axis factor, column jx
        int jx = tid;
        float w0 = pw[h * 3 + 0], w2 = pw[h * 3 + 2];
        float s[14]; float mx = -1e30f;
        #pragma unroll
        for (int ix = 0; ix < 14; ix++) {
            float dx = (float)(jx - ix);
            float v = w0 * dx + w2 * dx * dx;
            s[ix] = v; mx = fmaxf(mx, v);
        }
        float sum = 0.f;
        #pragma unroll
        for (int ix = 0; ix < 14; ix++) { s[ix] = expf(s[ix] - mx); sum += s[ix]; }
        float r = 1.0f / sum;
        #pragma unroll
        for (int ix = 0; ix < 14; ix++) sB[ix * 14 + jx] = s[ix] * r;
    } else if (tid >= 32 && tid < 46) {   // An: y-axis factor, column jy
        int jy = tid - 32;
        float w1 = pw[h * 3 + 1], w2 = pw[h * 3 + 2];
        float s[14]; float mx = -1e30f;
        #pragma unroll
        for (int iy = 0; iy < 14; iy++) {
            float dy = (float)(jy - iy);
            float v = w1 * dy + w2 * dy * dy;
            s[iy] = v; mx = fmaxf(mx, v);
        }
        float sum = 0.f;
        #pragma unroll
        for (int iy = 0; iy < 14; iy++) { s[iy] = expf(s[iy] - mx); sum += s[iy]; }
        float r = 1.0f / sum;
        #pragma unroll
        for (int iy = 0; iy < 14; iy++) sA[iy * 14 + jy] = s[iy] * r;
    }

    // token-stat prologue (inv only; mean/var loaded in epilogue from L2)
    {
        const float4* ig = (const float4*)(g_inv + (b * HEADS + h) * NT);
        float4* dI = (float4*)sINV;
        for (int i = tid; i < NT / 4; i += K2T) dI[i] = ig[i];
    }
    __syncthreads();

    int g = tid >> 5, cl = tid & 31;     // warp g in [0,7), rows g and g+7
    const float* xpg = &g_xp[(((size_t)(b * NCT + ctile)) * PP) * 32];

    // ---- stage 1: contract over ix, split jx into halves of 7 (reg diet)
    #pragma unroll 1
    for (int hf = 0; hf < 2; hf++) {
        int j0 = hf * 7;
        float a1[2][7], a2[2][7];
        #pragma unroll
        for (int jx = 0; jx < 7; jx++) { a1[0][jx] = a1[1][jx] = a2[0][jx] = a2[1][jx] = 0.f; }
        #pragma unroll
        for (int ix = 0; ix < 14; ix++) {
            float v0 = __ldg(xpg + (((g    ) * 14 + ix) << 5) + cl);
            float v1 = __ldg(xpg + (((g + 7) * 14 + ix) << 5) + cl);
            float q0 = v0 * v0, q1 = v1 * v1;
            #pragma unroll
            for (int jx = 0; jx < 7; jx++) {
                float p = sB[ix * 14 + j0 + jx];
                a1[0][jx] = fmaf(v0, p, a1[0][jx]);
                a2[0][jx] = fmaf(q0, p, a2[0][jx]);
                a1[1][jx] = fmaf(v1, p, a1[1][jx]);
                a2[1][jx] = fmaf(q1, p, a2[1][jx]);
            }
        }
        #pragma unroll
        for (int jx = 0; jx < 7; jx++) {
            sT1[(((g    ) * 14 + j0 + jx) << 5) + cl] = a1[0][jx];
            sT2[(((g    ) * 14 + j0 + jx) << 5) + cl] = a2[0][jx];
            sT1[(((g + 7) * 14 + j0 + jx) << 5) + cl] = a1[1][jx];
            sT2[(((g + 7) * 14 + j0 + jx) << 5) + cl] = a2[1][jx];
        }
    }
    __syncthreads();

    // ---- stage 2: contract over iy, split jx halves (read/write col-blocks
    // are disjoint per half, so one barrier between compute and write suffices)
    #pragma unroll 1
    for (int hf = 0; hf < 2; hf++) {
        int j0 = hf * 7;
        float m[2][7], m2[2][7];
        #pragma unroll
        for (int jx = 0; jx < 7; jx++) { m[0][jx] = m[1][jx] = m2[0][jx] = m2[1][jx] = 0.f; }
        #pragma unroll
        for (int iy = 0; iy < 14; iy++) {
            float p0 = sA[iy * 14 + g];
            float p1 = sA[iy * 14 + g + 7];
            #pragma unroll
            for (int jx = 0; jx < 7; jx++) {
                float t1v = sT1[((iy * 14 + j0 + jx) << 5) + cl];
                float t2v = sT2[((iy * 14 + j0 + jx) << 5) + cl];
                m [0][jx] = fmaf(p0, t1v, m [0][jx]);
                m2[0][jx] = fmaf(p0, t2v, m2[0][jx]);
                m [1][jx] = fmaf(p1, t1v, m [1][jx]);
                m2[1][jx] = fmaf(p1, t2v, m2[1][jx]);
            }
        }
        __syncthreads();   // all reads of this col-block done before overwrite
        #pragma unroll
        for (int jx = 0; jx < 7; jx++) {
            float mm = m[0][jx];
            sT1[(((g    ) * 14 + j0 + jx) << 5) + cl] = omm * mm;
            sT2[(((g    ) * 14 + j0 + jx) << 5) + cl] = omv * (m2[0][jx] - mm * mm);
            mm = m[1][jx];
            sT1[(((g + 7) * 14 + j0 + jx) << 5) + cl] = omm * mm;
            sT2[(((g + 7) * 14 + j0 + jx) << 5) + cl] = omv * (m2[1][jx] - mm * mm);
        }
    }
    __syncthreads();

    // ---- fused epilogue: stream x -> out (float4, 7-deep batched loads)
    int q = tid & 7;                     // float4 slot within 32-ch tile
    int tb = tid >> 3;                   // token slot 0..27
    float4 wv = ((const float4*)(weight + c0))[q];
    float4 bv = ((const float4*)(bias   + c0))[q];
    const float* mlg = g_mln + b * NT;
    const float* vlg = g_vln + b * NT;
    const float4* xr  = (const float4*)(x   + (size_t)b * NT * NC + c0);
    float4*       orr = (float4*)      (out + (size_t)b * NT * NC + c0);
    const int rs = NC / 4;               // row stride in float4

    #pragma unroll 1
    for (int it = it0; it < itN; ++it) {
        float4 xv[7];
        float ml[7], vl[7];
        #pragma unroll
        for (int u = 0; u < 7; u++) {
            int t = tb + (it * 7 + u) * 28;
            xv[u] = __ldg(&xr[(size_t)t * rs + q]);
            ml[u] = __ldg(mlg + t);
            vl[u] = __ldg(vlg + t);
        }
        #pragma unroll
        for (int u = 0; u < 7; u++) {
            int t = tb + (it * 7 + u) * 28;
            unsigned row = (unsigned)t / 28u;
            unsigned col = (unsigned)t - row * 28u;
            int j = (int)((row >> 1) * 14 + (col >> 1));
            float inv = sINV[t];
            float mlv = mwh * ml[u], vlv = vwh * vl[u];
            float4 mr = ((const float4*)(sT1 + (j << 5)))[q];
            float4 vr = ((const float4*)(sT2 + (j << 5)))[q];
            float4 o;
            o.x = (xv[u].x * inv - (mr.x + mlv)) * rsqrtf(vr.x + vlv + EPSF) * wv.x + bv.x;
            o.y = (xv[u].y * inv - (mr.y + mlv)) * rsqrtf(vr.y + vlv + EPSF) * wv.y + bv.y;
            o.z = (xv[u].z * inv - (mr.z + mlv)) * rsqrtf(vr.z + vlv + EPSF) * wv.z + bv.z;
            o.w = (xv[u].w * inv - (mr.w + mlv)) * rsqrtf(vr.w + vlv + EPSF) * wv.w + bv.w;
            orr[(size_t)t * rs + q] = o;
        }
    }
}

// ============================================================
extern "C" void kernel_launch(void* const* d_in, const int* in_sizes, int n_in,
                              void* d_out, int out_size) {
    const float* x      = (const float*)d_in[0];
    const float* weight = (const float*)d_in[1];
    const float* bias   = (const float*)d_in[2];
    const float* mnw    = (const float*)d_in[3];
    const float* vnw    = (const float*)d_in[4];
    const float* pw     = (const float*)d_in[5];
    // d_in[6] = pos_b: cancels inside the softmax, unused.
    float* out = (float*)d_out;

    cudaFuncSetAttribute(k2_main, cudaFuncAttributeMaxDynamicSharedMemorySize,
                         SM_FLOATS * (int)sizeof(float));

    k1_stats<<<NB * PP, 192>>>(x);
    k2_main<<<K2GRID, K2T, SM_FLOATS * sizeof(float)>>>(
        x, weight, bias, mnw, vnw, pw, out);
}

// round 12
// speedup vs baseline: 1.1588x; 1.1588x over previous
#include <cuda_runtime.h>
#include <math.h>

#define HEADS 4
#define RES 28
#define PSZ 14
#define PP 196
#define NB 32
#define NT 784
#define NC 768
#define CH 192
#define NCT 24            // channel tiles of 32
#define EPSF 1e-5f

// ---- persistent device scratch (no allocations allowed) ----
__device__ float g_xp[(size_t)NB * NCT * PP * 32];  // pooled xn, [b][ctile][patch][32]
__device__ float g_inv[NB * HEADS * NT];            // [b][h][t]
__device__ float g_mln[NB * NT];
__device__ float g_vln[NB * NT];

// ============================================================
// K1: per-token group stats + pooled xp.  block = (b, patch j)
// 192 threads; thread owns 4 consecutive channels (float4).
// ============================================================
__global__ void __launch_bounds__(192) k1_stats(const float* __restrict__ x) {
    int blk = blockIdx.x;
    int b = blk / PP, j = blk % PP;
    int py = j / 14, px = j % 14;
    int tid = threadIdx.x;
    int head = tid / 48;
    int c0 = head * CH + (tid % 48) * 4;
    int baseT = (2 * py) * 28 + 2 * px;

    float4 xv[4];
    float s1[4], s2[4];
    #pragma unroll
    for (int tok = 0; tok < 4; tok++) {
        int t = baseT + (tok >> 1) * 28 + (tok & 1);
        float4 v = __ldg((const float4*)(x + ((size_t)(b * NT + t)) * NC + c0));
        xv[tok] = v;
        s1[tok] = v.x + v.y + v.z + v.w;
        s2[tok] = v.x * v.x + v.y * v.y + v.z * v.z + v.w * v.w;
    }
    #pragma unroll
    for (int off = 8; off > 0; off >>= 1) {
        #pragma unroll
        for (int tok = 0; tok < 4; tok++) {
            s1[tok] += __shfl_down_sync(0xffffffffu, s1[tok], off, 16);
            s2[tok] += __shfl_down_sync(0xffffffffu, s2[tok], off, 16);
        }
    }
    __shared__ float rs1[12][4], rs2[12][4];            // [segment][tok]
    __shared__ float sS1[4][4], sS2[4][4], sInv[4][4];  // [tok][head]
    int seg = tid >> 4;
    if ((tid & 15) == 0) {
        #pragma unroll
        for (int tok = 0; tok < 4; tok++) { rs1[seg][tok] = s1[tok]; rs2[seg][tok] = s2[tok]; }
    }
    __syncthreads();
    if (tid < 16) {
        int tok = tid & 3, h = tid >> 2;
        float S1 = rs1[3 * h][tok] + rs1[3 * h + 1][tok] + rs1[3 * h + 2][tok];
        float S2 = rs2[3 * h][tok] + rs2[3 * h + 1][tok] + rs2[3 * h + 2][tok];
        float inv = rsqrtf(S2 * (1.0f / CH) + EPSF);
        sS1[tok][h] = S1; sS2[tok][h] = S2; sInv[tok][h] = inv;
        int t = baseT + (tok >> 1) * 28 + (tok & 1);
        g_inv[(b * HEADS + h) * NT + t] = inv;
    }
    __syncthreads();
    if (tid < 4) {
        int tok = tid;
        float sx = 0.f, sx2 = 0.f;
        #pragma unroll
        for (int h = 0; h < 4; h++) {
            float inv = sInv[tok][h];
            sx  += sS1[tok][h] * inv;
            sx2 += sS2[tok][h] * inv * inv;
        }
        float mean = sx * (1.0f / NC);
        float var = (sx2 - sx * mean) * (1.0f / (NC - 1));
        int t = baseT + (tok >> 1) * 28 + (tok & 1);
        g_mln[b * NT + t] = mean;
        g_vln[b * NT + t] = var;
    }
    float i0 = sInv[0][head], i1 = sInv[1][head], i2 = sInv[2][head], i3 = sInv[3][head];
    float4 o;
    o.x = 0.25f * (xv[0].x * i0 + xv[1].x * i1 + xv[2].x * i2 + xv[3].x * i3);
    o.y = 0.25f * (xv[0].y * i0 + xv[1].y * i1 + xv[2].y * i2 + xv[3].y * i3);
    o.z = 0.25f * (xv[0].z * i0 + xv[1].z * i1 + xv[2].z * i2 + xv[3].z * i3);
    o.w = 0.25f * (xv[0].w * i0 + xv[1].w * i1 + xv[2].w * i2 + xv[3].w * i3);
    int ct = c0 >> 5, ln = c0 & 31;
    *(float4*)&g_xp[(((size_t)(b * NCT + ct)) * PP + j) * 32 + ln] = o;
}

// ============================================================
// K2: separable pos-mix + fused output epilogue.
// block = (b, 32-channel tile). 224 threads = 7 warps; warp g owns rows g, g+7.
// stage-1 inputs hoisted to block top (latency behind prologue);
// epilogue software-pipelined, iter-0 x batch prefetched under stage-2.
// ============================================================
#define K2T 224
#define SM_FLOATS (12544 + 784 + 392)   // sT1,sT2 + sINV + sA,sB

__global__ void __launch_bounds__(K2T, 4) k2_main(
        const float* __restrict__ x, const float* __restrict__ weight,
        const float* __restrict__ bias, const float* __restrict__ mnw,
        const float* __restrict__ vnw, const float* __restrict__ pw,
        float* __restrict__ out) {
    extern __shared__ float sm[];
    float* sT1  = sm;              // 196x32 stage-1 mean     (later: scaled mean_r)
    float* sT2  = sm + 6272;       // 196x32 stage-1 sq-mean  (later: scaled var_r)
    float* sINV = sm + 12544;      // 784  inv for this head
    float* sA   = sm + 13328;      // 196  y-factor [iy*14+jy]
    float* sB   = sm + 13524;      // 196  x-factor [ix*14+jx]

    int b = blockIdx.x;
    int ctile = blockIdx.y;
    int c0 = ctile * 32;
    int h = ctile / 6;             // 6 tiles per head
    int tid = threadIdx.x;
    int g = tid >> 5, cl = tid & 31;     // warp g in [0,7), rows g and g+7

    // ---- hoisted stage-1 loads (latency hides behind factors + prologue + barrier)
    const float* xpg = &g_xp[(((size_t)(b * NCT + ctile)) * PP) * 32];
    float v0[14], v1[14];
    #pragma unroll
    for (int ix = 0; ix < 14; ix++) {
        v0[ix] = __ldg(xpg + (((g    ) * 14 + ix) << 5) + cl);
        v1[ix] = __ldg(xpg + (((g + 7) * 14 + ix) << 5) + cl);
    }

    float mwh = 1.0f / (1.0f + expf(-mnw[h]));
    float vwh = 1.0f / (1.0f + expf(-vnw[h]));
    float omm = 1.0f - mwh, omv = 1.0f - vwh;

    // in-block separable softmax factors (pos_b cancels in softmax)
    if (tid < 14) {                       // Bn: x-axis factor, column jx
        int jx = tid;
        float w0 = pw[h * 3 + 0], w2 = pw[h * 3 + 2];
        float s[14]; float mx = -1e30f;
        #pragma unroll
        for (int ix = 0; ix < 14; ix++) {
            float dx = (float)(jx - ix);
            float v = w0 * dx + w2 * dx * dx;
            s[ix] = v; mx = fmaxf(mx, v);
        }
        float sum = 0.f;
        #pragma unroll
        for (int ix = 0; ix < 14; ix++) { s[ix] = expf(s[ix] - mx); sum += s[ix]; }
        float r = 1.0f / sum;
        #pragma unroll
        for (int ix = 0; ix < 14; ix++) sB[ix * 14 + jx] = s[ix] * r;
    } else if (tid >= 32 && tid < 46) {   // An: y-axis factor, column jy
        int jy = tid - 32;
        float w1 = pw[h * 3 + 1], w2 = pw[h * 3 + 2];
        float s[14]; float mx = -1e30f;
        #pragma unroll
        for (int iy = 0; iy < 14; iy++) {
            float dy = (float)(jy - iy);
            float v = w1 * dy + w2 * dy * dy;
            s[iy] = v; mx = fmaxf(mx, v);
        }
        float sum = 0.f;
        #pragma unroll
        for (int iy = 0; iy < 14; iy++) { s[iy] = expf(s[iy] - mx); sum += s[iy]; }
        float r = 1.0f / sum;
        #pragma unroll
        for (int iy = 0; iy < 14; iy++) sA[iy * 14 + jy] = s[iy] * r;
    }

    // token-stat prologue (inv only; mean/var loaded in epilogue from L2)
    {
        const float4* ig = (const float4*)(g_inv + (b * HEADS + h) * NT);
        float4* dI = (float4*)sINV;
        for (int i = tid; i < NT / 4; i += K2T) dI[i] = ig[i];
    }
    __syncthreads();

    // ---- stage 1: contract over ix from registers, jx halves of 7
    #pragma unroll 1
    for (int hf = 0; hf < 2; hf++) {
        int j0 = hf * 7;
        float a1[2][7], a2[2][7];
        #pragma unroll
        for (int jx = 0; jx < 7; jx++) { a1[0][jx] = a1[1][jx] = a2[0][jx] = a2[1][jx] = 0.f; }
        #pragma unroll
        for (int ix = 0; ix < 14; ix++) {
            float x0 = v0[ix], x1 = v1[ix];
            float q0 = x0 * x0, q1 = x1 * x1;
            #pragma unroll
            for (int jx = 0; jx < 7; jx++) {
                float p = sB[ix * 14 + j0 + jx];
                a1[0][jx] = fmaf(x0, p, a1[0][jx]);
                a2[0][jx] = fmaf(q0, p, a2[0][jx]);
                a1[1][jx] = fmaf(x1, p, a1[1][jx]);
                a2[1][jx] = fmaf(q1, p, a2[1][jx]);
            }
        }
        #pragma unroll
        for (int jx = 0; jx < 7; jx++) {
            sT1[(((g    ) * 14 + j0 + jx) << 5) + cl] = a1[0][jx];
            sT2[(((g    ) * 14 + j0 + jx) << 5) + cl] = a2[0][jx];
            sT1[(((g + 7) * 14 + j0 + jx) << 5) + cl] = a1[1][jx];
            sT2[(((g + 7) * 14 + j0 + jx) << 5) + cl] = a2[1][jx];
        }
    }
    __syncthreads();

    // ---- prefetch epilogue iter-0 x batch (DRAM fetch overlaps stage-2 FMA)
    int q = tid & 7;                     // float4 slot within 32-ch tile
    int tb = tid >> 3;                   // image column 0..27 (constant per thread)
    int jcol = tb >> 1;                  // patch column (constant)
    const float4* xr  = (const float4*)(x   + (size_t)b * NT * NC + c0);
    const int rs = NC / 4;               // row stride in float4
    float4 xa[4];
    #pragma unroll
    for (int u = 0; u < 4; u++)
        xa[u] = __ldg(&xr[(size_t)(u * 28 + tb) * rs + q]);

    // ---- stage 2: contract over iy, jx halves; in-place write after barrier
    #pragma unroll 1
    for (int hf = 0; hf < 2; hf++) {
        int j0 = hf * 7;
        float m[2][7], m2[2][7];
        #pragma unroll
        for (int jx = 0; jx < 7; jx++) { m[0][jx] = m[1][jx] = m2[0][jx] = m2[1][jx] = 0.f; }
        #pragma unroll
        for (int iy = 0; iy < 14; iy++) {
            float p0 = sA[iy * 14 + g];
            float p1 = sA[iy * 14 + g + 7];
            #pragma unroll
            for (int jx = 0; jx < 7; jx++) {
                float t1v = sT1[((iy * 14 + j0 + jx) << 5) + cl];
                float t2v = sT2[((iy * 14 + j0 + jx) << 5) + cl];
                m [0][jx] = fmaf(p0, t1v, m [0][jx]);
                m2[0][jx] = fmaf(p0, t2v, m2[0][jx]);
                m [1][jx] = fmaf(p1, t1v, m [1][jx]);
                m2[1][jx] = fmaf(p1, t2v, m2[1][jx]);
            }
        }
        __syncthreads();   // all reads of this col-block done before overwrite
        #pragma unroll
        for (int jx = 0; jx < 7; jx++) {
            float mm = m[0][jx];
            sT1[(((g    ) * 14 + j0 + jx) << 5) + cl] = omm * mm;
            sT2[(((g    ) * 14 + j0 + jx) << 5) + cl] = omv * (m2[0][jx] - mm * mm);
            mm = m[1][jx];
            sT1[(((g + 7) * 14 + j0 + jx) << 5) + cl] = omm * mm;
            sT2[(((g + 7) * 14 + j0 + jx) << 5) + cl] = omv * (m2[1][jx] - mm * mm);
        }
    }
    __syncthreads();

    // ---- fused epilogue: software-pipelined stream x -> out
    float4 wv = ((const float4*)(weight + c0))[q];
    float4 bv = ((const float4*)(bias   + c0))[q];
    const float* mlg = g_mln + b * NT;
    const float* vlg = g_vln + b * NT;
    float*       orr0 = out + (size_t)b * NT * NC + c0;
    float4*      orr  = (float4*)orr0;

    float mla[4], vla[4];
    #pragma unroll
    for (int u = 0; u < 4; u++) {
        int t = u * 28 + tb;
        mla[u] = __ldg(mlg + t);
        vla[u] = __ldg(vlg + t);
    }

    #pragma unroll
    for (int it = 0; it < 7; ++it) {
        float4 xb[4]; float mlb[4], vlb[4];
        if (it < 6) {
            #pragma unroll
            for (int u = 0; u < 4; u++) {
                int t = ((it + 1) * 4 + u) * 28 + tb;
                xb[u]  = __ldg(&xr[(size_t)t * rs + q]);
                mlb[u] = __ldg(mlg + t);
                vlb[u] = __ldg(vlg + t);
            }
        }
        #pragma unroll
        for (int u = 0; u < 4; u++) {
            int row = it * 4 + u;
            int t = row * 28 + tb;
            int j = (row >> 1) * 14 + jcol;
            float inv = sINV[t];
            float mlv = mwh * mla[u], vlv = vwh * vla[u];
            float4 mr = ((const float4*)(sT1 + (j << 5)))[q];
            float4 vr = ((const float4*)(sT2 + (j << 5)))[q];
            float4 o;
            o.x = (xa[u].x * inv - (mr.x + mlv)) * rsqrtf(vr.x + vlv + EPSF) * wv.x + bv.x;
            o.y = (xa[u].y * inv - (mr.y + mlv)) * rsqrtf(vr.y + vlv + EPSF) * wv.y + bv.y;
            o.z = (xa[u].z * inv - (mr.z + mlv)) * rsqrtf(vr.z + vlv + EPSF) * wv.z + bv.z;
            o.w = (xa[u].w * inv - (mr.w + mlv)) * rsqrtf(vr.w + vlv + EPSF) * wv.w + bv.w;
            orr[(size_t)t * rs + q] = o;
        }
        #pragma unroll
        for (int u = 0; u < 4; u++) { xa[u] = xb[u]; mla[u] = mlb[u]; vla[u] = vlb[u]; }
    }
}

// ============================================================
extern "C" void kernel_launch(void* const* d_in, const int* in_sizes, int n_in,
                              void* d_out, int out_size) {
    const float* x      = (const float*)d_in[0];
    const float* weight = (const float*)d_in[1];
    const float* bias   = (const float*)d_in[2];
    const float* mnw    = (const float*)d_in[3];
    const float* vnw    = (const float*)d_in[4];
    const float* pw     = (const float*)d_in[5];
    // d_in[6] = pos_b: cancels inside the softmax, unused.
    float* out = (float*)d_out;

    cudaFuncSetAttribute(k2_main, cudaFuncAttributeMaxDynamicSharedMemorySize,
                         SM_FLOATS * (int)sizeof(float));

    k1_stats<<<NB * PP, 192>>>(x);
    k2_main<<<dim3(NB, NCT), K2T, SM_FLOATS * sizeof(float)>>>(
        x, weight, bias, mnw, vnw, pw, out);
}

// round 13
// speedup vs baseline: 1.1868x; 1.0242x over previous
#include <cuda_runtime.h>
#include <math.h>

#define HEADS 4
#define RES 28
#define PSZ 14
#define PP 196
#define NB 32
#define NT 784
#define NC 768
#define CH 192
#define NCT 24            // channel tiles of 32
#define EPSF 1e-5f

// ---- persistent device scratch (no allocations allowed) ----
__device__ float g_xp[(size_t)NB * NCT * PP * 32];  // pooled xn, [b][ctile][patch][32]
__device__ float g_inv[NB * HEADS * NT];            // [b][h][t]
__device__ float g_mln[NB * NT];
__device__ float g_vln[NB * NT];

// ============================================================
// K1: per-token group stats + pooled xp.  block = (b, patch j)
// 192 threads; thread owns 4 consecutive channels (float4).
// ============================================================
__global__ void __launch_bounds__(192) k1_stats(const float* __restrict__ x) {
    int blk = blockIdx.x;
    int b = blk / PP, j = blk % PP;
    int py = j / 14, px = j % 14;
    int tid = threadIdx.x;
    int head = tid / 48;
    int c0 = head * CH + (tid % 48) * 4;
    int baseT = (2 * py) * 28 + 2 * px;

    float4 xv[4];
    float s1[4], s2[4];
    #pragma unroll
    for (int tok = 0; tok < 4; tok++) {
        int t = baseT + (tok >> 1) * 28 + (tok & 1);
        float4 v = __ldg((const float4*)(x + ((size_t)(b * NT + t)) * NC + c0));
        xv[tok] = v;
        s1[tok] = v.x + v.y + v.z + v.w;
        s2[tok] = v.x * v.x + v.y * v.y + v.z * v.z + v.w * v.w;
    }
    #pragma unroll
    for (int off = 8; off > 0; off >>= 1) {
        #pragma unroll
        for (int tok = 0; tok < 4; tok++) {
            s1[tok] += __shfl_down_sync(0xffffffffu, s1[tok], off, 16);
            s2[tok] += __shfl_down_sync(0xffffffffu, s2[tok], off, 16);
        }
    }
    __shared__ float rs1[12][4], rs2[12][4];            // [segment][tok]
    __shared__ float sS1[4][4], sS2[4][4], sInv[4][4];  // [tok][head]
    int seg = tid >> 4;
    if ((tid & 15) == 0) {
        #pragma unroll
        for (int tok = 0; tok < 4; tok++) { rs1[seg][tok] = s1[tok]; rs2[seg][tok] = s2[tok]; }
    }
    __syncthreads();
    if (tid < 16) {
        int tok = tid & 3, h = tid >> 2;
        float S1 = rs1[3 * h][tok] + rs1[3 * h + 1][tok] + rs1[3 * h + 2][tok];
        float S2 = rs2[3 * h][tok] + rs2[3 * h + 1][tok] + rs2[3 * h + 2][tok];
        float inv = rsqrtf(S2 * (1.0f / CH) + EPSF);
        sS1[tok][h] = S1; sS2[tok][h] = S2; sInv[tok][h] = inv;
        int t = baseT + (tok >> 1) * 28 + (tok & 1);
        g_inv[(b * HEADS + h) * NT + t] = inv;
    }
    __syncthreads();
    if (tid < 4) {
        int tok = tid;
        float sx = 0.f, sx2 = 0.f;
        #pragma unroll
        for (int h = 0; h < 4; h++) {
            float inv = sInv[tok][h];
            sx  += sS1[tok][h] * inv;
            sx2 += sS2[tok][h] * inv * inv;
        }
        float mean = sx * (1.0f / NC);
        float var = (sx2 - sx * mean) * (1.0f / (NC - 1));
        int t = baseT + (tok >> 1) * 28 + (tok & 1);
        g_mln[b * NT + t] = mean;
        g_vln[b * NT + t] = var;
    }
    float i0 = sInv[0][head], i1 = sInv[1][head], i2 = sInv[2][head], i3 = sInv[3][head];
    float4 o;
    o.x = 0.25f * (xv[0].x * i0 + xv[1].x * i1 + xv[2].x * i2 + xv[3].x * i3);
    o.y = 0.25f * (xv[0].y * i0 + xv[1].y * i1 + xv[2].y * i2 + xv[3].y * i3);
    o.z = 0.25f * (xv[0].z * i0 + xv[1].z * i1 + xv[2].z * i2 + xv[3].z * i3);
    o.w = 0.25f * (xv[0].w * i0 + xv[1].w * i1 + xv[2].w * i2 + xv[3].w * i3);
    int ct = c0 >> 5, ln = c0 & 31;
    *(float4*)&g_xp[(((size_t)(b * NCT + ct)) * PP + j) * 32 + ln] = o;
}

// ============================================================
// K2: separable pos-mix + fused output epilogue.
// block = (b, 32-channel tile). 224 threads = 7 warps; warp g owns rows g, g+7.
// stage-1 inputs hoisted; epilogue software-pipelined; out written
// evict-first (__stcs) so it never displaces x from L2.
// ============================================================
#define K2T 224
#define SM_FLOATS (12544 + 784 + 392)   // sT1,sT2 + sINV + sA,sB

__global__ void __launch_bounds__(K2T, 4) k2_main(
        const float* __restrict__ x, const float* __restrict__ weight,
        const float* __restrict__ bias, const float* __restrict__ mnw,
        const float* __restrict__ vnw, const float* __restrict__ pw,
        float* __restrict__ out) {
    extern __shared__ float sm[];
    float* sT1  = sm;              // 196x32 stage-1 mean     (later: scaled mean_r)
    float* sT2  = sm + 6272;       // 196x32 stage-1 sq-mean  (later: scaled var_r)
    float* sINV = sm + 12544;      // 784  inv for this head
    float* sA   = sm + 13328;      // 196  y-factor [iy*14+jy]
    float* sB   = sm + 13524;      // 196  x-factor [ix*14+jx]

    int b = blockIdx.x;
    int ctile = blockIdx.y;
    int c0 = ctile * 32;
    int h = ctile / 6;             // 6 tiles per head
    int tid = threadIdx.x;
    int g = tid >> 5, cl = tid & 31;     // warp g in [0,7), rows g and g+7

    // ---- hoisted stage-1 loads (latency hides behind factors + prologue + barrier)
    const float* xpg = &g_xp[(((size_t)(b * NCT + ctile)) * PP) * 32];
    float v0[14], v1[14];
    #pragma unroll
    for (int ix = 0; ix < 14; ix++) {
        v0[ix] = __ldg(xpg + (((g    ) * 14 + ix) << 5) + cl);
        v1[ix] = __ldg(xpg + (((g + 7) * 14 + ix) << 5) + cl);
    }

    float mwh = 1.0f / (1.0f + expf(-mnw[h]));
    float vwh = 1.0f / (1.0f + expf(-vnw[h]));
    float omm = 1.0f - mwh, omv = 1.0f - vwh;

    // in-block separable softmax factors (pos_b cancels in softmax)
    if (tid < 14) {                       // Bn: x-axis factor, column jx
        int jx = tid;
        float w0 = pw[h * 3 + 0], w2 = pw[h * 3 + 2];
        float s[14]; float mx = -1e30f;
        #pragma unroll
        for (int ix = 0; ix < 14; ix++) {
            float dx = (float)(jx - ix);
            float v = w0 * dx + w2 * dx * dx;
            s[ix] = v; mx = fmaxf(mx, v);
        }
        float sum = 0.f;
        #pragma unroll
        for (int ix = 0; ix < 14; ix++) { s[ix] = expf(s[ix] - mx); sum += s[ix]; }
        float r = 1.0f / sum;
        #pragma unroll
        for (int ix = 0; ix < 14; ix++) sB[ix * 14 + jx] = s[ix] * r;
    } else if (tid >= 32 && tid < 46) {   // An: y-axis factor, column jy
        int jy = tid - 32;
        float w1 = pw[h * 3 + 1], w2 = pw[h * 3 + 2];
        float s[14]; float mx = -1e30f;
        #pragma unroll
        for (int iy = 0; iy < 14; iy++) {
            float dy = (float)(jy - iy);
            float v = w1 * dy + w2 * dy * dy;
            s[iy] = v; mx = fmaxf(mx, v);
        }
        float sum = 0.f;
        #pragma unroll
        for (int iy = 0; iy < 14; iy++) { s[iy] = expf(s[iy] - mx); sum += s[iy]; }
        float r = 1.0f / sum;
        #pragma unroll
        for (int iy = 0; iy < 14; iy++) sA[iy * 14 + jy] = s[iy] * r;
    }

    // token-stat prologue (inv only; mean/var loaded in epilogue from L2)
    {
        const float4* ig = (const float4*)(g_inv + (b * HEADS + h) * NT);
        float4* dI = (float4*)sINV;
        for (int i = tid; i < NT / 4; i += K2T) dI[i] = ig[i];
    }
    __syncthreads();

    // ---- stage 1: contract over ix from registers, jx halves of 7
    #pragma unroll 1
    for (int hf = 0; hf < 2; hf++) {
        int j0 = hf * 7;
        float a1[2][7], a2[2][7];
        #pragma unroll
        for (int jx = 0; jx < 7; jx++) { a1[0][jx] = a1[1][jx] = a2[0][jx] = a2[1][jx] = 0.f; }
        #pragma unroll
        for (int ix = 0; ix < 14; ix++) {
            float x0 = v0[ix], x1 = v1[ix];
            float q0 = x0 * x0, q1 = x1 * x1;
            #pragma unroll
            for (int jx = 0; jx < 7; jx++) {
                float p = sB[ix * 14 + j0 + jx];
                a1[0][jx] = fmaf(x0, p, a1[0][jx]);
                a2[0][jx] = fmaf(q0, p, a2[0][jx]);
                a1[1][jx] = fmaf(x1, p, a1[1][jx]);
                a2[1][jx] = fmaf(q1, p, a2[1][jx]);
            }
        }
        #pragma unroll
        for (int jx = 0; jx < 7; jx++) {
            sT1[(((g    ) * 14 + j0 + jx) << 5) + cl] = a1[0][jx];
            sT2[(((g    ) * 14 + j0 + jx) << 5) + cl] = a2[0][jx];
            sT1[(((g + 7) * 14 + j0 + jx) << 5) + cl] = a1[1][jx];
            sT2[(((g + 7) * 14 + j0 + jx) << 5) + cl] = a2[1][jx];
        }
    }
    __syncthreads();

    // ---- prefetch epilogue iter-0 x batch (DRAM fetch overlaps stage-2 FMA)
    int q = tid & 7;                     // float4 slot within 32-ch tile
    int tb = tid >> 3;                   // image column 0..27 (constant per thread)
    int jcol = tb >> 1;                  // patch column (constant)
    const float4* xr  = (const float4*)(x   + (size_t)b * NT * NC + c0);
    const int rs = NC / 4;               // row stride in float4
    float4 xa[4];
    #pragma unroll
    for (int u = 0; u < 4; u++)
        xa[u] = __ldg(&xr[(size_t)(u * 28 + tb) * rs + q]);

    // ---- stage 2: contract over iy, jx halves; in-place write after barrier
    #pragma unroll 1
    for (int hf = 0; hf < 2; hf++) {
        int j0 = hf * 7;
        float m[2][7], m2[2][7];
        #pragma unroll
        for (int jx = 0; jx < 7; jx++) { m[0][jx] = m[1][jx] = m2[0][jx] = m2[1][jx] = 0.f; }
        #pragma unroll
        for (int iy = 0; iy < 14; iy++) {
            float p0 = sA[iy * 14 + g];
            float p1 = sA[iy * 14 + g + 7];
            #pragma unroll
            for (int jx = 0; jx < 7; jx++) {
                float t1v = sT1[((iy * 14 + j0 + jx) << 5) + cl];
                float t2v = sT2[((iy * 14 + j0 + jx) << 5) + cl];
                m [0][jx] = fmaf(p0, t1v, m [0][jx]);
                m2[0][jx] = fmaf(p0, t2v, m2[0][jx]);
                m [1][jx] = fmaf(p1, t1v, m [1][jx]);
                m2[1][jx] = fmaf(p1, t2v, m2[1][jx]);
            }
        }
        __syncthreads();   // all reads of this col-block done before overwrite
        #pragma unroll
        for (int jx = 0; jx < 7; jx++) {
            float mm = m[0][jx];
            sT1[(((g    ) * 14 + j0 + jx) << 5) + cl] = omm * mm;
            sT2[(((g    ) * 14 + j0 + jx) << 5) + cl] = omv * (m2[0][jx] - mm * mm);
            mm = m[1][jx];
            sT1[(((g + 7) * 14 + j0 + jx) << 5) + cl] = omm * mm;
            sT2[(((g + 7) * 14 + j0 + jx) << 5) + cl] = omv * (m2[1][jx] - mm * mm);
        }
    }
    __syncthreads();

    // ---- fused epilogue: software-pipelined stream x -> out
    float4 wv = ((const float4*)(weight + c0))[q];
    float4 bv = ((const float4*)(bias   + c0))[q];
    const float* mlg = g_mln + b * NT;
    const float* vlg = g_vln + b * NT;
    float*       orr0 = out + (size_t)b * NT * NC + c0;
    float4*      orr  = (float4*)orr0;

    float mla[4], vla[4];
    #pragma unroll
    for (int u = 0; u < 4; u++) {
        int t = u * 28 + tb;
        mla[u] = __ldg(mlg + t);
        vla[u] = __ldg(vlg + t);
    }

    #pragma unroll
    for (int it = 0; it < 7; ++it) {
        float4 xb[4]; float mlb[4], vlb[4];
        if (it < 6) {
            #pragma unroll
            for (int u = 0; u < 4; u++) {
                int t = ((it + 1) * 4 + u) * 28 + tb;
                xb[u]  = __ldg(&xr[(size_t)t * rs + q]);
                mlb[u] = __ldg(mlg + t);
                vlb[u] = __ldg(vlg + t);
            }
        }
        #pragma unroll
        for (int u = 0; u < 4; u++) {
            int row = it * 4 + u;
            int t = row * 28 + tb;
            int j = (row >> 1) * 14 + jcol;
            float inv = sINV[t];
            float mlv = mwh * mla[u], vlv = vwh * vla[u];
            float4 mr = ((const float4*)(sT1 + (j << 5)))[q];
            float4 vr = ((const float4*)(sT2 + (j << 5)))[q];
            float4 o;
            o.x = (xa[u].x * inv - (mr.x + mlv)) * rsqrtf(vr.x + vlv + EPSF) * wv.x + bv.x;
            o.y = (xa[u].y * inv - (mr.y + mlv)) * rsqrtf(vr.y + vlv + EPSF) * wv.y + bv.y;
            o.z = (xa[u].z * inv - (mr.z + mlv)) * rsqrtf(vr.z + vlv + EPSF) * wv.z + bv.z;
            o.w = (xa[u].w * inv - (mr.w + mlv)) * rsqrtf(vr.w + vlv + EPSF) * wv.w + bv.w;
            __stcs(&orr[(size_t)t * rs + q], o);   // evict-first: out never re-read
        }
        #pragma unroll
        for (int u = 0; u < 4; u++) { xa[u] = xb[u]; mla[u] = mlb[u]; vla[u] = vlb[u]; }
    }
}

// ============================================================
extern "C" void kernel_launch(void* const* d_in, const int* in_sizes, int n_in,
                              void* d_out, int out_size) {
    const float* x      = (const float*)d_in[0];
    const float* weight = (const float*)d_in[1];
    const float* bias   = (const float*)d_in[2];
    const float* mnw    = (const float*)d_in[3];
    const float* vnw    = (const float*)d_in[4];
    const float* pw     = (const float*)d_in[5];
    // d_in[6] = pos_b: cancels inside the softmax, unused.
    float* out = (float*)d_out;

    cudaFuncSetAttribute(k2_main, cudaFuncAttributeMaxDynamicSharedMemorySize,
                         SM_FLOATS * (int)sizeof(float));

    k1_stats<<<NB * PP, 192>>>(x);
    k2_main<<<dim3(NB, NCT), K2T, SM_FLOATS * sizeof(float)>>>(
        x, weight, bias, mnw, vnw, pw, out);
}